// round 2
// baseline (speedup 1.0000x reference)
#include <cuda_runtime.h>

#define MAXN 100000
#define NROWS 128

// Persistent scratch (no allocations allowed). float4 for 16B alignment.
__device__ float4 g_h4[MAXN * 16];    // h:   N x 64
__device__ float4 g_M4[MAXN * 16];    // M:   N x 64 (per-node message)
__device__ float4 g_agg4[MAXN * 16];  // agg: N x 64

// ---------------------------------------------------------------------------
// h = relu(x @ w_in + b_in)   (x: N x 3, w_in: 3 x 64)
// ---------------------------------------------------------------------------
__global__ void __launch_bounds__(256) input_kernel(
    const float* __restrict__ x, const float* __restrict__ w_in,
    const float* __restrict__ b_in, int N) {
  int i = blockIdx.x * blockDim.x + threadIdx.x;
  if (i >= N * 64) return;
  int node = i >> 6, c = i & 63;
  float acc = __ldg(b_in + c);
  float x0 = __ldg(x + node * 3 + 0);
  float x1 = __ldg(x + node * 3 + 1);
  float x2 = __ldg(x + node * 3 + 2);
  acc = fmaf(x0, __ldg(w_in + c), acc);
  acc = fmaf(x1, __ldg(w_in + 64 + c), acc);
  acc = fmaf(x2, __ldg(w_in + 128 + c), acc);
  ((float*)g_h4)[i] = fmaxf(acc, 0.f);
}

// ---------------------------------------------------------------------------
// M = relu(h @ W1 + b1) @ W2 + b2  (per-node message MLP, fused 2-stage GEMM)
// Block: 128 threads (16x8), tile 128 rows x 64 cols, 8x8 per thread.
// A-tile stored transposed [k][row] in smem -> conflict-free float4 LDS.
// ---------------------------------------------------------------------------
__global__ void __launch_bounds__(128) msg_kernel(
    const float* __restrict__ W1, const float* __restrict__ B1,
    const float* __restrict__ W2, const float* __restrict__ B2, int N) {
  extern __shared__ float sm[];
  float* as  = sm;              // 64 * 128 (A transposed, reused for t)
  float* w1s = sm + 64 * 128;   // 64 * 64
  float* w2s = w1s + 64 * 64;   // 64 * 64

  const float* hin = (const float*)g_h4;
  float* Mout = (float*)g_M4;
  int tid = threadIdx.x;
  int rb = blockIdx.x * NROWS;

#pragma unroll
  for (int i = tid; i < 1024; i += 128) {
    ((float4*)w1s)[i] = __ldg((const float4*)W1 + i);
    ((float4*)w2s)[i] = __ldg((const float4*)W2 + i);
  }
  {
    int r = tid, grow = rb + r;
    if (grow < N) {
      const float4* src = (const float4*)(hin + (size_t)grow * 64);
#pragma unroll
      for (int kq = 0; kq < 16; kq++) {
        float4 v = src[kq];
        as[(kq * 4 + 0) * 128 + r] = v.x;
        as[(kq * 4 + 1) * 128 + r] = v.y;
        as[(kq * 4 + 2) * 128 + r] = v.z;
        as[(kq * 4 + 3) * 128 + r] = v.w;
      }
    } else {
#pragma unroll
      for (int k = 0; k < 64; k++) as[k * 128 + r] = 0.f;
    }
  }
  __syncthreads();

  int ty = tid >> 3, tx = tid & 7;
  int r0 = ty * 8, c0 = tx * 8;

  float acc[8][8];
#pragma unroll
  for (int rr = 0; rr < 8; rr++)
#pragma unroll
    for (int cc = 0; cc < 8; cc++) acc[rr][cc] = 0.f;

#pragma unroll 4
  for (int k = 0; k < 64; k++) {
    const float4* ap = (const float4*)(as + k * 128 + r0);
    float4 a0 = ap[0], a1 = ap[1];
    const float4* bp = (const float4*)(w1s + k * 64 + c0);
    float4 b0 = bp[0], b1 = bp[1];
    float av[8] = {a0.x, a0.y, a0.z, a0.w, a1.x, a1.y, a1.z, a1.w};
    float bv[8] = {b0.x, b0.y, b0.z, b0.w, b1.x, b1.y, b1.z, b1.w};
#pragma unroll
    for (int rr = 0; rr < 8; rr++)
#pragma unroll
      for (int cc = 0; cc < 8; cc++)
        acc[rr][cc] = fmaf(av[rr], bv[cc], acc[rr][cc]);
  }

  __syncthreads();  // stage-1 reads of `as` done; overwrite with t (transposed)
#pragma unroll
  for (int cc = 0; cc < 8; cc++) {
    float b = __ldg(B1 + c0 + cc);
#pragma unroll
    for (int rr = 0; rr < 8; rr++)
      as[(c0 + cc) * 128 + (r0 + rr)] = fmaxf(acc[rr][cc] + b, 0.f);
  }
  __syncthreads();

#pragma unroll
  for (int rr = 0; rr < 8; rr++)
#pragma unroll
    for (int cc = 0; cc < 8; cc++) acc[rr][cc] = 0.f;

#pragma unroll 4
  for (int k = 0; k < 64; k++) {
    const float4* ap = (const float4*)(as + k * 128 + r0);
    float4 a0 = ap[0], a1 = ap[1];
    const float4* bp = (const float4*)(w2s + k * 64 + c0);
    float4 b0 = bp[0], b1 = bp[1];
    float av[8] = {a0.x, a0.y, a0.z, a0.w, a1.x, a1.y, a1.z, a1.w};
    float bv[8] = {b0.x, b0.y, b0.z, b0.w, b1.x, b1.y, b1.z, b1.w};
#pragma unroll
    for (int rr = 0; rr < 8; rr++)
#pragma unroll
      for (int cc = 0; cc < 8; cc++)
        acc[rr][cc] = fmaf(av[rr], bv[cc], acc[rr][cc]);
  }

  float b2v[8];
#pragma unroll
  for (int cc = 0; cc < 8; cc++) b2v[cc] = __ldg(B2 + c0 + cc);
#pragma unroll
  for (int rr = 0; rr < 8; rr++) {
    int grow = rb + r0 + rr;
    if (grow >= N) continue;
    float4 o0 = make_float4(acc[rr][0] + b2v[0], acc[rr][1] + b2v[1],
                            acc[rr][2] + b2v[2], acc[rr][3] + b2v[3]);
    float4 o1 = make_float4(acc[rr][4] + b2v[4], acc[rr][5] + b2v[5],
                            acc[rr][6] + b2v[6], acc[rr][7] + b2v[7]);
    float4* dst = (float4*)(Mout + (size_t)grow * 64 + c0);
    dst[0] = o0;
    dst[1] = o1;
  }
}

// ---------------------------------------------------------------------------
// agg = 0
// ---------------------------------------------------------------------------
__global__ void __launch_bounds__(256) zero_kernel(int n4) {
  int i = blockIdx.x * blockDim.x + threadIdx.x;
  if (i < n4) g_agg4[i] = make_float4(0.f, 0.f, 0.f, 0.f);
}

// ---------------------------------------------------------------------------
// agg[dst] += M[src]  (16 float4 per edge, vector red.global on sm_90+)
// ---------------------------------------------------------------------------
__global__ void __launch_bounds__(256) scatter_kernel(
    const int* __restrict__ ei, int E) {
  long i = (long)blockIdx.x * blockDim.x + threadIdx.x;
  long total = (long)E * 16;
  if (i >= total) return;
  int e = (int)(i >> 4), q = (int)(i & 15);
  int src = __ldg(ei + e);
  int dst = __ldg(ei + E + e);
  float4 v = __ldg(&g_M4[(size_t)src * 16 + q]);
  atomicAdd(&g_agg4[(size_t)dst * 16 + q], v);
}

// ---------------------------------------------------------------------------
// hn = relu([h,agg] @ W1 + b1) @ W2 + b2 ; bn ; h = relu(hn + h)   (in place)
// Same blocking as msg_kernel but K=128 in stage 1.
// t reuses rows [64..128) of the A-tile; rows [0..64) (= old h) kept for the
// residual.
// ---------------------------------------------------------------------------
__global__ void __launch_bounds__(128) upd_kernel(
    const float* __restrict__ W1, const float* __restrict__ B1,
    const float* __restrict__ W2, const float* __restrict__ B2,
    const float* __restrict__ Gm, const float* __restrict__ Bt,
    const float* __restrict__ Mn, const float* __restrict__ Vr, int N) {
  extern __shared__ float sm[];
  float* as  = sm;                // 128 * 128  ([k][row]; k<64:h, k>=64:agg/t)
  float* w1s = sm + 128 * 128;    // 128 * 64
  float* w2s = w1s + 128 * 64;    // 64 * 64

  float* hio = (float*)g_h4;
  const float* agg = (const float*)g_agg4;
  int tid = threadIdx.x;
  int rb = blockIdx.x * NROWS;

#pragma unroll
  for (int i = tid; i < 2048; i += 128)
    ((float4*)w1s)[i] = __ldg((const float4*)W1 + i);
#pragma unroll
  for (int i = tid; i < 1024; i += 128)
    ((float4*)w2s)[i] = __ldg((const float4*)W2 + i);
  {
    int r = tid, grow = rb + r;
    if (grow < N) {
      const float4* s1 = (const float4*)(hio + (size_t)grow * 64);
      const float4* s2 = (const float4*)(agg + (size_t)grow * 64);
#pragma unroll
      for (int kq = 0; kq < 16; kq++) {
        float4 v = s1[kq];
        as[(kq * 4 + 0) * 128 + r] = v.x;
        as[(kq * 4 + 1) * 128 + r] = v.y;
        as[(kq * 4 + 2) * 128 + r] = v.z;
        as[(kq * 4 + 3) * 128 + r] = v.w;
        float4 u = s2[kq];
        as[(64 + kq * 4 + 0) * 128 + r] = u.x;
        as[(64 + kq * 4 + 1) * 128 + r] = u.y;
        as[(64 + kq * 4 + 2) * 128 + r] = u.z;
        as[(64 + kq * 4 + 3) * 128 + r] = u.w;
      }
    } else {
#pragma unroll
      for (int k = 0; k < 128; k++) as[k * 128 + r] = 0.f;
    }
  }
  __syncthreads();

  int ty = tid >> 3, tx = tid & 7;
  int r0 = ty * 8, c0 = tx * 8;

  float acc[8][8];
#pragma unroll
  for (int rr = 0; rr < 8; rr++)
#pragma unroll
    for (int cc = 0; cc < 8; cc++) acc[rr][cc] = 0.f;

#pragma unroll 4
  for (int k = 0; k < 128; k++) {
    const float4* ap = (const float4*)(as + k * 128 + r0);
    float4 a0 = ap[0], a1 = ap[1];
    const float4* bp = (const float4*)(w1s + k * 64 + c0);
    float4 b0 = bp[0], b1 = bp[1];
    float av[8] = {a0.x, a0.y, a0.z, a0.w, a1.x, a1.y, a1.z, a1.w};
    float bv[8] = {b0.x, b0.y, b0.z, b0.w, b1.x, b1.y, b1.z, b1.w};
#pragma unroll
    for (int rr = 0; rr < 8; rr++)
#pragma unroll
      for (int cc = 0; cc < 8; cc++)
        acc[rr][cc] = fmaf(av[rr], bv[cc], acc[rr][cc]);
  }

  __syncthreads();  // write t into rows [64..128) (agg half no longer needed)
#pragma unroll
  for (int cc = 0; cc < 8; cc++) {
    float b = __ldg(B1 + c0 + cc);
#pragma unroll
    for (int rr = 0; rr < 8; rr++)
      as[(64 + c0 + cc) * 128 + (r0 + rr)] = fmaxf(acc[rr][cc] + b, 0.f);
  }
  __syncthreads();

#pragma unroll
  for (int rr = 0; rr < 8; rr++)
#pragma unroll
    for (int cc = 0; cc < 8; cc++) acc[rr][cc] = 0.f;

#pragma unroll 4
  for (int k = 0; k < 64; k++) {
    const float4* ap = (const float4*)(as + (64 + k) * 128 + r0);
    float4 a0 = ap[0], a1 = ap[1];
    const float4* bp = (const float4*)(w2s + k * 64 + c0);
    float4 b0 = bp[0], b1 = bp[1];
    float av[8] = {a0.x, a0.y, a0.z, a0.w, a1.x, a1.y, a1.z, a1.w};
    float bv[8] = {b0.x, b0.y, b0.z, b0.w, b1.x, b1.y, b1.z, b1.w};
#pragma unroll
    for (int rr = 0; rr < 8; rr++)
#pragma unroll
      for (int cc = 0; cc < 8; cc++)
        acc[rr][cc] = fmaf(av[rr], bv[cc], acc[rr][cc]);
  }

  float sc[8], sh[8], b2v[8];
#pragma unroll
  for (int cc = 0; cc < 8; cc++) {
    int c = c0 + cc;
    float s = __ldg(Gm + c) * rsqrtf(__ldg(Vr + c) + 1e-5f);
    sc[cc] = s;
    sh[cc] = __ldg(Bt + c) - __ldg(Mn + c) * s;
    b2v[cc] = __ldg(B2 + c);
  }
#pragma unroll
  for (int rr = 0; rr < 8; rr++) {
    int grow = rb + r0 + rr;
    if (grow >= N) continue;
    float o[8];
#pragma unroll
    for (int cc = 0; cc < 8; cc++) {
      float hn = acc[rr][cc] + b2v[cc];
      float hold = as[(c0 + cc) * 128 + (r0 + rr)];  // old h (rows <64 intact)
      o[cc] = fmaxf(fmaf(hn, sc[cc], sh[cc]) + hold, 0.f);
    }
    float4* dst = (float4*)(hio + (size_t)grow * 64 + c0);
    dst[0] = make_float4(o[0], o[1], o[2], o[3]);
    dst[1] = make_float4(o[4], o[5], o[6], o[7]);
  }
}

// ---------------------------------------------------------------------------
// out = relu(h[:NQ] @ out_w1 + b1) @ out_w2 + b2   (64->32->1, warp per node)
// ---------------------------------------------------------------------------
__global__ void __launch_bounds__(256) out_kernel(
    const float* __restrict__ w1, const float* __restrict__ b1,
    const float* __restrict__ w2, const float* __restrict__ b2,
    float* __restrict__ out, int NQ) {
  int warp = (blockIdx.x * blockDim.x + threadIdx.x) >> 5;
  int lane = threadIdx.x & 31;
  if (warp >= NQ) return;
  const float* h = (const float*)g_h4;
  float2 hv = ((const float2*)(h + (size_t)warp * 64))[lane];
  float acc = __ldg(b1 + lane);
#pragma unroll
  for (int kk = 0; kk < 32; kk++) {
    float hx = __shfl_sync(0xffffffffu, hv.x, kk);
    float hy = __shfl_sync(0xffffffffu, hv.y, kk);
    acc = fmaf(hx, __ldg(w1 + (2 * kk) * 32 + lane), acc);
    acc = fmaf(hy, __ldg(w1 + (2 * kk + 1) * 32 + lane), acc);
  }
  float v = fmaxf(acc, 0.f) * __ldg(w2 + lane);
#pragma unroll
  for (int o = 16; o; o >>= 1) v += __shfl_down_sync(0xffffffffu, v, o);
  if (lane == 0) out[warp] = v + __ldg(b2);
}

// ---------------------------------------------------------------------------
extern "C" void kernel_launch(void* const* d_in, const int* in_sizes, int n_in,
                              void* d_out, int out_size) {
  // Inputs (metadata order): x, edge_index, [n_qubits], w_in, b_in,
  // msg_w1, msg_b1, msg_w2, msg_b2, upd_w1, upd_b1, upd_w2, upd_b2,
  // bn_g, bn_b, bn_m, bn_v, out_w1, out_b1, out_w2, out_b2
  int off = (n_in >= 21) ? 1 : 0;  // n_qubits present as a size-1 tensor?
  const float* x      = (const float*)d_in[0];
  const int*   ei     = (const int*)d_in[1];
  const float* w_in   = (const float*)d_in[2 + off];
  const float* b_in   = (const float*)d_in[3 + off];
  const float* msg_w1 = (const float*)d_in[4 + off];
  const float* msg_b1 = (const float*)d_in[5 + off];
  const float* msg_w2 = (const float*)d_in[6 + off];
  const float* msg_b2 = (const float*)d_in[7 + off];
  const float* upd_w1 = (const float*)d_in[8 + off];
  const float* upd_b1 = (const float*)d_in[9 + off];
  const float* upd_w2 = (const float*)d_in[10 + off];
  const float* upd_b2 = (const float*)d_in[11 + off];
  const float* bn_g   = (const float*)d_in[12 + off];
  const float* bn_b   = (const float*)d_in[13 + off];
  const float* bn_m   = (const float*)d_in[14 + off];
  const float* bn_v   = (const float*)d_in[15 + off];
  const float* out_w1 = (const float*)d_in[16 + off];
  const float* out_b1 = (const float*)d_in[17 + off];
  const float* out_w2 = (const float*)d_in[18 + off];
  const float* out_b2 = (const float*)d_in[19 + off];

  int N = in_sizes[0] / 3;
  int E = in_sizes[1] / 2;
  int L = in_sizes[4 + off] / (64 * 64);
  int NQ = out_size;

  const int MSG_SMEM = (64 * 128 + 2 * 64 * 64) * 4;             // 64 KB
  const int UPD_SMEM = (128 * 128 + 128 * 64 + 64 * 64) * 4;     // 112 KB
  cudaFuncSetAttribute(msg_kernel, cudaFuncAttributeMaxDynamicSharedMemorySize,
                       MSG_SMEM);
  cudaFuncSetAttribute(upd_kernel, cudaFuncAttributeMaxDynamicSharedMemorySize,
                       UPD_SMEM);

  int gb = (N + NROWS - 1) / NROWS;

  input_kernel<<<(N * 64 + 255) / 256, 256>>>(x, w_in, b_in, N);

  for (int l = 0; l < L; l++) {
    msg_kernel<<<gb, 128, MSG_SMEM>>>(msg_w1 + l * 4096, msg_b1 + l * 64,
                                      msg_w2 + l * 4096, msg_b2 + l * 64, N);
    zero_kernel<<<(N * 16 + 255) / 256, 256>>>(N * 16);
    long items = (long)E * 16;
    scatter_kernel<<<(int)((items + 255) / 256), 256>>>(ei, E);
    upd_kernel<<<gb, 128, UPD_SMEM>>>(
        upd_w1 + l * 8192, upd_b1 + l * 64, upd_w2 + l * 4096, upd_b2 + l * 64,
        bn_g + l * 64, bn_b + l * 64, bn_m + l * 64, bn_v + l * 64, N);
  }

  out_kernel<<<(NQ * 32 + 255) / 256, 256>>>(out_w1, out_b1, out_w2, out_b2,
                                             (float*)d_out, NQ);
}

// round 3
// speedup vs baseline: 1.2904x; 1.2904x over previous
#include <cuda_runtime.h>
#include <cuda_fp16.h>

#define MAXN 100000
#define MAXE 1600000
#define NROWS 128

// Persistent scratch (no allocations allowed).
__device__ float4 g_h4[MAXN * 16];    // h:   N x 64 (fp32)
__device__ float4 g_Mh4[MAXN * 8];    // M:   N x 64 (fp16, packed half2 x32)
__device__ float4 g_agg4[MAXN * 16];  // agg: N x 64 (fp32)
// CSR (built once per launch from edge_index)
__device__ int g_counts[MAXN];
__device__ int g_rowstart[MAXN];
__device__ int g_rowend[MAXN];  // fill-cursor; equals row end after fill
__device__ int g_csrsrc[MAXE];
__device__ int g_blocksum[128];

// ---------------------------------------------------------------------------
// h = relu(x @ w_in + b_in)   (x: N x 3, w_in: 3 x 64)
// ---------------------------------------------------------------------------
__global__ void __launch_bounds__(256) input_kernel(
    const float* __restrict__ x, const float* __restrict__ w_in,
    const float* __restrict__ b_in, int N) {
  int i = blockIdx.x * blockDim.x + threadIdx.x;
  if (i >= N * 64) return;
  int node = i >> 6, c = i & 63;
  float acc = __ldg(b_in + c);
  float x0 = __ldg(x + node * 3 + 0);
  float x1 = __ldg(x + node * 3 + 1);
  float x2 = __ldg(x + node * 3 + 2);
  acc = fmaf(x0, __ldg(w_in + c), acc);
  acc = fmaf(x1, __ldg(w_in + 64 + c), acc);
  acc = fmaf(x2, __ldg(w_in + 128 + c), acc);
  ((float*)g_h4)[i] = fmaxf(acc, 0.f);
}

// ---------------------------------------------------------------------------
// CSR build: counts -> scan -> fill (src array sorted by dst)
// ---------------------------------------------------------------------------
__global__ void __launch_bounds__(256) zero_counts_kernel(int N) {
  int i = blockIdx.x * blockDim.x + threadIdx.x;
  if (i < N) g_counts[i] = 0;
}

__global__ void __launch_bounds__(256) hist_kernel(const int* __restrict__ ei,
                                                   int E) {
  int e = blockIdx.x * blockDim.x + threadIdx.x;
  if (e < E) atomicAdd(&g_counts[__ldg(ei + E + e)], 1);
}

__global__ void __launch_bounds__(1024) scan1_kernel(int N) {
  __shared__ int sh[1024];
  int t = threadIdx.x;
  int idx = blockIdx.x * 1024 + t;
  int v = (idx < N) ? g_counts[idx] : 0;
  sh[t] = v;
  __syncthreads();
#pragma unroll
  for (int off = 1; off < 1024; off <<= 1) {
    int x = (t >= off) ? sh[t - off] : 0;
    __syncthreads();
    sh[t] += x;
    __syncthreads();
  }
  if (idx < N) g_rowstart[idx] = sh[t] - v;  // exclusive within block
  if (t == 1023) g_blocksum[blockIdx.x] = sh[1023];
}

__global__ void scan2_kernel(int nb) {
  if (threadIdx.x == 0 && blockIdx.x == 0) {
    int acc = 0;
    for (int i = 0; i < nb; i++) {
      int tmp = g_blocksum[i];
      g_blocksum[i] = acc;
      acc += tmp;
    }
  }
}

__global__ void __launch_bounds__(256) scan3_kernel(int N) {
  int i = blockIdx.x * blockDim.x + threadIdx.x;
  if (i < N) {
    int v = g_rowstart[i] + g_blocksum[i >> 10];
    g_rowstart[i] = v;
    g_rowend[i] = v;  // cursor init
  }
}

__global__ void __launch_bounds__(256) fill_kernel(const int* __restrict__ ei,
                                                   int E) {
  int e = blockIdx.x * blockDim.x + threadIdx.x;
  if (e < E) {
    int d = __ldg(ei + E + e);
    int pos = atomicAdd(&g_rowend[d], 1);
    g_csrsrc[pos] = __ldg(ei + e);
  }
}

// ---------------------------------------------------------------------------
// agg[i] = sum_{e: dst(e)=i} M[src(e)]   (warp per node, conflict-free)
// M is fp16: each lane accumulates 2 columns (half2 -> float2).
// ---------------------------------------------------------------------------
__global__ void __launch_bounds__(256) gather_kernel(int N) {
  int w = (blockIdx.x * blockDim.x + threadIdx.x) >> 5;
  int lane = threadIdx.x & 31;
  if (w >= N) return;
  int s = __ldg(&g_rowstart[w]);
  int e = __ldg(&g_rowend[w]);
  const __half2* M = (const __half2*)g_Mh4;
  float2 a0 = make_float2(0.f, 0.f), a1 = make_float2(0.f, 0.f);
  int j = s;
  for (; j + 2 <= e; j += 2) {
    int s0 = __ldg(&g_csrsrc[j]);
    int s1 = __ldg(&g_csrsrc[j + 1]);
    float2 v0 = __half22float2(__ldg(&M[(size_t)s0 * 32 + lane]));
    float2 v1 = __half22float2(__ldg(&M[(size_t)s1 * 32 + lane]));
    a0.x += v0.x;
    a0.y += v0.y;
    a1.x += v1.x;
    a1.y += v1.y;
  }
  if (j < e) {
    int s0 = __ldg(&g_csrsrc[j]);
    float2 v0 = __half22float2(__ldg(&M[(size_t)s0 * 32 + lane]));
    a0.x += v0.x;
    a0.y += v0.y;
  }
  ((float2*)g_agg4)[(size_t)w * 32 + lane] =
      make_float2(a0.x + a1.x, a0.y + a1.y);
}

// ---------------------------------------------------------------------------
// M = relu(h @ W1 + b1) @ W2 + b2  (per-node message MLP, fused 2-stage GEMM)
// Output stored as fp16 (half2) for cheap gather.
// ---------------------------------------------------------------------------
__global__ void __launch_bounds__(128) msg_kernel(
    const float* __restrict__ W1, const float* __restrict__ B1,
    const float* __restrict__ W2, const float* __restrict__ B2, int N) {
  extern __shared__ float sm[];
  float* as  = sm;              // 64 * 128 (A transposed, reused for t)
  float* w1s = sm + 64 * 128;   // 64 * 64
  float* w2s = w1s + 64 * 64;   // 64 * 64

  const float* hin = (const float*)g_h4;
  int tid = threadIdx.x;
  int rb = blockIdx.x * NROWS;

#pragma unroll
  for (int i = tid; i < 1024; i += 128) {
    ((float4*)w1s)[i] = __ldg((const float4*)W1 + i);
    ((float4*)w2s)[i] = __ldg((const float4*)W2 + i);
  }
  {
    int r = tid, grow = rb + r;
    if (grow < N) {
      const float4* src = (const float4*)(hin + (size_t)grow * 64);
#pragma unroll
      for (int kq = 0; kq < 16; kq++) {
        float4 v = src[kq];
        as[(kq * 4 + 0) * 128 + r] = v.x;
        as[(kq * 4 + 1) * 128 + r] = v.y;
        as[(kq * 4 + 2) * 128 + r] = v.z;
        as[(kq * 4 + 3) * 128 + r] = v.w;
      }
    } else {
#pragma unroll
      for (int k = 0; k < 64; k++) as[k * 128 + r] = 0.f;
    }
  }
  __syncthreads();

  int ty = tid >> 3, tx = tid & 7;
  int r0 = ty * 8, c0 = tx * 8;

  float acc[8][8];
#pragma unroll
  for (int rr = 0; rr < 8; rr++)
#pragma unroll
    for (int cc = 0; cc < 8; cc++) acc[rr][cc] = 0.f;

#pragma unroll 4
  for (int k = 0; k < 64; k++) {
    const float4* ap = (const float4*)(as + k * 128 + r0);
    float4 a0 = ap[0], a1 = ap[1];
    const float4* bp = (const float4*)(w1s + k * 64 + c0);
    float4 b0 = bp[0], b1 = bp[1];
    float av[8] = {a0.x, a0.y, a0.z, a0.w, a1.x, a1.y, a1.z, a1.w};
    float bv[8] = {b0.x, b0.y, b0.z, b0.w, b1.x, b1.y, b1.z, b1.w};
#pragma unroll
    for (int rr = 0; rr < 8; rr++)
#pragma unroll
      for (int cc = 0; cc < 8; cc++)
        acc[rr][cc] = fmaf(av[rr], bv[cc], acc[rr][cc]);
  }

  __syncthreads();
#pragma unroll
  for (int cc = 0; cc < 8; cc++) {
    float b = __ldg(B1 + c0 + cc);
#pragma unroll
    for (int rr = 0; rr < 8; rr++)
      as[(c0 + cc) * 128 + (r0 + rr)] = fmaxf(acc[rr][cc] + b, 0.f);
  }
  __syncthreads();

#pragma unroll
  for (int rr = 0; rr < 8; rr++)
#pragma unroll
    for (int cc = 0; cc < 8; cc++) acc[rr][cc] = 0.f;

#pragma unroll 4
  for (int k = 0; k < 64; k++) {
    const float4* ap = (const float4*)(as + k * 128 + r0);
    float4 a0 = ap[0], a1 = ap[1];
    const float4* bp = (const float4*)(w2s + k * 64 + c0);
    float4 b0 = bp[0], b1 = bp[1];
    float av[8] = {a0.x, a0.y, a0.z, a0.w, a1.x, a1.y, a1.z, a1.w};
    float bv[8] = {b0.x, b0.y, b0.z, b0.w, b1.x, b1.y, b1.z, b1.w};
#pragma unroll
    for (int rr = 0; rr < 8; rr++)
#pragma unroll
      for (int cc = 0; cc < 8; cc++)
        acc[rr][cc] = fmaf(av[rr], bv[cc], acc[rr][cc]);
  }

  float b2v[8];
#pragma unroll
  for (int cc = 0; cc < 8; cc++) b2v[cc] = __ldg(B2 + c0 + cc);
#pragma unroll
  for (int rr = 0; rr < 8; rr++) {
    int grow = rb + r0 + rr;
    if (grow >= N) continue;
    __half2 p0 = __floats2half2_rn(acc[rr][0] + b2v[0], acc[rr][1] + b2v[1]);
    __half2 p1 = __floats2half2_rn(acc[rr][2] + b2v[2], acc[rr][3] + b2v[3]);
    __half2 p2 = __floats2half2_rn(acc[rr][4] + b2v[4], acc[rr][5] + b2v[5]);
    __half2 p3 = __floats2half2_rn(acc[rr][6] + b2v[6], acc[rr][7] + b2v[7]);
    uint4 u;
    u.x = *reinterpret_cast<unsigned*>(&p0);
    u.y = *reinterpret_cast<unsigned*>(&p1);
    u.z = *reinterpret_cast<unsigned*>(&p2);
    u.w = *reinterpret_cast<unsigned*>(&p3);
    ((uint4*)g_Mh4)[(size_t)grow * 8 + (c0 >> 3)] = u;
  }
}

// ---------------------------------------------------------------------------
// hn = relu([h,agg] @ W1 + b1) @ W2 + b2 ; bn ; h = relu(hn + h)   (in place)
// ---------------------------------------------------------------------------
__global__ void __launch_bounds__(128) upd_kernel(
    const float* __restrict__ W1, const float* __restrict__ B1,
    const float* __restrict__ W2, const float* __restrict__ B2,
    const float* __restrict__ Gm, const float* __restrict__ Bt,
    const float* __restrict__ Mn, const float* __restrict__ Vr, int N) {
  extern __shared__ float sm[];
  float* as  = sm;                // 128 * 128  ([k][row]; k<64:h, k>=64:agg/t)
  float* w1s = sm + 128 * 128;    // 128 * 64
  float* w2s = w1s + 128 * 64;    // 64 * 64

  float* hio = (float*)g_h4;
  const float* agg = (const float*)g_agg4;
  int tid = threadIdx.x;
  int rb = blockIdx.x * NROWS;

#pragma unroll
  for (int i = tid; i < 2048; i += 128)
    ((float4*)w1s)[i] = __ldg((const float4*)W1 + i);
#pragma unroll
  for (int i = tid; i < 1024; i += 128)
    ((float4*)w2s)[i] = __ldg((const float4*)W2 + i);
  {
    int r = tid, grow = rb + r;
    if (grow < N) {
      const float4* s1 = (const float4*)(hio + (size_t)grow * 64);
      const float4* s2 = (const float4*)(agg + (size_t)grow * 64);
#pragma unroll
      for (int kq = 0; kq < 16; kq++) {
        float4 v = s1[kq];
        as[(kq * 4 + 0) * 128 + r] = v.x;
        as[(kq * 4 + 1) * 128 + r] = v.y;
        as[(kq * 4 + 2) * 128 + r] = v.z;
        as[(kq * 4 + 3) * 128 + r] = v.w;
        float4 u = s2[kq];
        as[(64 + kq * 4 + 0) * 128 + r] = u.x;
        as[(64 + kq * 4 + 1) * 128 + r] = u.y;
        as[(64 + kq * 4 + 2) * 128 + r] = u.z;
        as[(64 + kq * 4 + 3) * 128 + r] = u.w;
      }
    } else {
#pragma unroll
      for (int k = 0; k < 128; k++) as[k * 128 + r] = 0.f;
    }
  }
  __syncthreads();

  int ty = tid >> 3, tx = tid & 7;
  int r0 = ty * 8, c0 = tx * 8;

  float acc[8][8];
#pragma unroll
  for (int rr = 0; rr < 8; rr++)
#pragma unroll
    for (int cc = 0; cc < 8; cc++) acc[rr][cc] = 0.f;

#pragma unroll 4
  for (int k = 0; k < 128; k++) {
    const float4* ap = (const float4*)(as + k * 128 + r0);
    float4 a0 = ap[0], a1 = ap[1];
    const float4* bp = (const float4*)(w1s + k * 64 + c0);
    float4 b0 = bp[0], b1 = bp[1];
    float av[8] = {a0.x, a0.y, a0.z, a0.w, a1.x, a1.y, a1.z, a1.w};
    float bv[8] = {b0.x, b0.y, b0.z, b0.w, b1.x, b1.y, b1.z, b1.w};
#pragma unroll
    for (int rr = 0; rr < 8; rr++)
#pragma unroll
      for (int cc = 0; cc < 8; cc++)
        acc[rr][cc] = fmaf(av[rr], bv[cc], acc[rr][cc]);
  }

  __syncthreads();
#pragma unroll
  for (int cc = 0; cc < 8; cc++) {
    float b = __ldg(B1 + c0 + cc);
#pragma unroll
    for (int rr = 0; rr < 8; rr++)
      as[(64 + c0 + cc) * 128 + (r0 + rr)] = fmaxf(acc[rr][cc] + b, 0.f);
  }
  __syncthreads();

#pragma unroll
  for (int rr = 0; rr < 8; rr++)
#pragma unroll
    for (int cc = 0; cc < 8; cc++) acc[rr][cc] = 0.f;

#pragma unroll 4
  for (int k = 0; k < 64; k++) {
    const float4* ap = (const float4*)(as + (64 + k) * 128 + r0);
    float4 a0 = ap[0], a1 = ap[1];
    const float4* bp = (const float4*)(w2s + k * 64 + c0);
    float4 b0 = bp[0], b1 = bp[1];
    float av[8] = {a0.x, a0.y, a0.z, a0.w, a1.x, a1.y, a1.z, a1.w};
    float bv[8] = {b0.x, b0.y, b0.z, b0.w, b1.x, b1.y, b1.z, b1.w};
#pragma unroll
    for (int rr = 0; rr < 8; rr++)
#pragma unroll
      for (int cc = 0; cc < 8; cc++)
        acc[rr][cc] = fmaf(av[rr], bv[cc], acc[rr][cc]);
  }

  float sc[8], sh[8], b2v[8];
#pragma unroll
  for (int cc = 0; cc < 8; cc++) {
    int c = c0 + cc;
    float s = __ldg(Gm + c) * rsqrtf(__ldg(Vr + c) + 1e-5f);
    sc[cc] = s;
    sh[cc] = __ldg(Bt + c) - __ldg(Mn + c) * s;
    b2v[cc] = __ldg(B2 + c);
  }
#pragma unroll
  for (int rr = 0; rr < 8; rr++) {
    int grow = rb + r0 + rr;
    if (grow >= N) continue;
    float o[8];
#pragma unroll
    for (int cc = 0; cc < 8; cc++) {
      float hn = acc[rr][cc] + b2v[cc];
      float hold = as[(c0 + cc) * 128 + (r0 + rr)];  // old h (rows <64 intact)
      o[cc] = fmaxf(fmaf(hn, sc[cc], sh[cc]) + hold, 0.f);
    }
    float4* dst = (float4*)(hio + (size_t)grow * 64 + c0);
    dst[0] = make_float4(o[0], o[1], o[2], o[3]);
    dst[1] = make_float4(o[4], o[5], o[6], o[7]);
  }
}

// ---------------------------------------------------------------------------
// out = relu(h[:NQ] @ out_w1 + b1) @ out_w2 + b2   (64->32->1, warp per node)
// ---------------------------------------------------------------------------
__global__ void __launch_bounds__(256) out_kernel(
    const float* __restrict__ w1, const float* __restrict__ b1,
    const float* __restrict__ w2, const float* __restrict__ b2,
    float* __restrict__ out, int NQ) {
  int warp = (blockIdx.x * blockDim.x + threadIdx.x) >> 5;
  int lane = threadIdx.x & 31;
  if (warp >= NQ) return;
  const float* h = (const float*)g_h4;
  float2 hv = ((const float2*)(h + (size_t)warp * 64))[lane];
  float acc = __ldg(b1 + lane);
#pragma unroll
  for (int kk = 0; kk < 32; kk++) {
    float hx = __shfl_sync(0xffffffffu, hv.x, kk);
    float hy = __shfl_sync(0xffffffffu, hv.y, kk);
    acc = fmaf(hx, __ldg(w1 + (2 * kk) * 32 + lane), acc);
    acc = fmaf(hy, __ldg(w1 + (2 * kk + 1) * 32 + lane), acc);
  }
  float v = fmaxf(acc, 0.f) * __ldg(w2 + lane);
#pragma unroll
  for (int o = 16; o; o >>= 1) v += __shfl_down_sync(0xffffffffu, v, o);
  if (lane == 0) out[warp] = v + __ldg(b2);
}

// ---------------------------------------------------------------------------
extern "C" void kernel_launch(void* const* d_in, const int* in_sizes, int n_in,
                              void* d_out, int out_size) {
  int off = (n_in >= 21) ? 1 : 0;  // n_qubits present as a size-1 tensor?
  const float* x      = (const float*)d_in[0];
  const int*   ei     = (const int*)d_in[1];
  const float* w_in   = (const float*)d_in[2 + off];
  const float* b_in   = (const float*)d_in[3 + off];
  const float* msg_w1 = (const float*)d_in[4 + off];
  const float* msg_b1 = (const float*)d_in[5 + off];
  const float* msg_w2 = (const float*)d_in[6 + off];
  const float* msg_b2 = (const float*)d_in[7 + off];
  const float* upd_w1 = (const float*)d_in[8 + off];
  const float* upd_b1 = (const float*)d_in[9 + off];
  const float* upd_w2 = (const float*)d_in[10 + off];
  const float* upd_b2 = (const float*)d_in[11 + off];
  const float* bn_g   = (const float*)d_in[12 + off];
  const float* bn_b   = (const float*)d_in[13 + off];
  const float* bn_m   = (const float*)d_in[14 + off];
  const float* bn_v   = (const float*)d_in[15 + off];
  const float* out_w1 = (const float*)d_in[16 + off];
  const float* out_b1 = (const float*)d_in[17 + off];
  const float* out_w2 = (const float*)d_in[18 + off];
  const float* out_b2 = (const float*)d_in[19 + off];

  int N = in_sizes[0] / 3;
  int E = in_sizes[1] / 2;
  int L = in_sizes[4 + off] / (64 * 64);
  int NQ = out_size;

  const int MSG_SMEM = (64 * 128 + 2 * 64 * 64) * 4;             // 64 KB
  const int UPD_SMEM = (128 * 128 + 128 * 64 + 64 * 64) * 4;     // 112 KB
  cudaFuncSetAttribute(msg_kernel, cudaFuncAttributeMaxDynamicSharedMemorySize,
                       MSG_SMEM);
  cudaFuncSetAttribute(upd_kernel, cudaFuncAttributeMaxDynamicSharedMemorySize,
                       UPD_SMEM);

  int gb = (N + NROWS - 1) / NROWS;
  int nb_scan = (N + 1023) / 1024;

  input_kernel<<<(N * 64 + 255) / 256, 256>>>(x, w_in, b_in, N);

  // CSR build (once; reused by all 5 layers)
  zero_counts_kernel<<<(N + 255) / 256, 256>>>(N);
  hist_kernel<<<(E + 255) / 256, 256>>>(ei, E);
  scan1_kernel<<<nb_scan, 1024>>>(N);
  scan2_kernel<<<1, 32>>>(nb_scan);
  scan3_kernel<<<(N + 255) / 256, 256>>>(N);
  fill_kernel<<<(E + 255) / 256, 256>>>(ei, E);

  for (int l = 0; l < L; l++) {
    msg_kernel<<<gb, 128, MSG_SMEM>>>(msg_w1 + l * 4096, msg_b1 + l * 64,
                                      msg_w2 + l * 4096, msg_b2 + l * 64, N);
    gather_kernel<<<(N * 32 + 255) / 256, 256>>>(N);
    upd_kernel<<<gb, 128, UPD_SMEM>>>(
        upd_w1 + l * 8192, upd_b1 + l * 64, upd_w2 + l * 4096, upd_b2 + l * 64,
        bn_g + l * 64, bn_b + l * 64, bn_m + l * 64, bn_v + l * 64, N);
  }

  out_kernel<<<(NQ * 32 + 255) / 256, 256>>>(out_w1, out_b1, out_w2, out_b2,
                                             (float*)d_out, NQ);
}

// round 4
// speedup vs baseline: 1.5033x; 1.1649x over previous
#include <cuda_runtime.h>
#include <cuda_fp16.h>
#include <mma.h>

using namespace nvcuda;

#define MAXN 100000
#define MAXE 1600000
#define NROWS 128

// Persistent scratch (no allocations allowed).
__device__ float4 g_h4[MAXN * 16];    // h:   N x 64 (fp32)
__device__ float4 g_Mh4[MAXN * 8];    // M:   N x 64 (fp16, packed)
__device__ float4 g_agg4[MAXN * 16];  // agg: N x 64 (fp32)
// CSR (built once per launch from edge_index)
__device__ int g_counts[MAXN];
__device__ int g_rowstart[MAXN];
__device__ int g_rowend[MAXN];
__device__ int g_csrsrc[MAXE];
__device__ int g_blocksum[128];

// ---------------------------------------------------------------------------
// h = relu(x @ w_in + b_in)   (x: N x 3, w_in: 3 x 64)
// ---------------------------------------------------------------------------
__global__ void __launch_bounds__(256) input_kernel(
    const float* __restrict__ x, const float* __restrict__ w_in,
    const float* __restrict__ b_in, int N) {
  int i = blockIdx.x * blockDim.x + threadIdx.x;
  if (i >= N * 64) return;
  int node = i >> 6, c = i & 63;
  float acc = __ldg(b_in + c);
  acc = fmaf(__ldg(x + node * 3 + 0), __ldg(w_in + c), acc);
  acc = fmaf(__ldg(x + node * 3 + 1), __ldg(w_in + 64 + c), acc);
  acc = fmaf(__ldg(x + node * 3 + 2), __ldg(w_in + 128 + c), acc);
  ((float*)g_h4)[i] = fmaxf(acc, 0.f);
}

// ---------------------------------------------------------------------------
// CSR build: counts -> scan -> fill (src array sorted by dst)
// ---------------------------------------------------------------------------
__global__ void __launch_bounds__(256) zero_counts_kernel(int N) {
  int i = blockIdx.x * blockDim.x + threadIdx.x;
  if (i < N) g_counts[i] = 0;
}

__global__ void __launch_bounds__(256) hist_kernel(const int* __restrict__ ei,
                                                   int E) {
  int e = blockIdx.x * blockDim.x + threadIdx.x;
  if (e < E) atomicAdd(&g_counts[__ldg(ei + E + e)], 1);
}

__global__ void __launch_bounds__(1024) scan1_kernel(int N) {
  __shared__ int sh[1024];
  int t = threadIdx.x;
  int idx = blockIdx.x * 1024 + t;
  int v = (idx < N) ? g_counts[idx] : 0;
  sh[t] = v;
  __syncthreads();
#pragma unroll
  for (int off = 1; off < 1024; off <<= 1) {
    int x = (t >= off) ? sh[t - off] : 0;
    __syncthreads();
    sh[t] += x;
    __syncthreads();
  }
  if (idx < N) g_rowstart[idx] = sh[t] - v;
  if (t == 1023) g_blocksum[blockIdx.x] = sh[1023];
}

__global__ void scan2_kernel(int nb) {
  if (threadIdx.x == 0 && blockIdx.x == 0) {
    int acc = 0;
    for (int i = 0; i < nb; i++) {
      int tmp = g_blocksum[i];
      g_blocksum[i] = acc;
      acc += tmp;
    }
  }
}

__global__ void __launch_bounds__(256) scan3_kernel(int N) {
  int i = blockIdx.x * blockDim.x + threadIdx.x;
  if (i < N) {
    int v = g_rowstart[i] + g_blocksum[i >> 10];
    g_rowstart[i] = v;
    g_rowend[i] = v;
  }
}

__global__ void __launch_bounds__(256) fill_kernel(const int* __restrict__ ei,
                                                   int E) {
  int e = blockIdx.x * blockDim.x + threadIdx.x;
  if (e < E) {
    int d = __ldg(ei + E + e);
    int pos = atomicAdd(&g_rowend[d], 1);
    g_csrsrc[pos] = __ldg(ei + e);
  }
}

// ---------------------------------------------------------------------------
// agg[i] = sum_{e: dst(e)=i} M[src(e)]   (warp per node, conflict-free)
// ---------------------------------------------------------------------------
__global__ void __launch_bounds__(256) gather_kernel(int N) {
  int w = (blockIdx.x * blockDim.x + threadIdx.x) >> 5;
  int lane = threadIdx.x & 31;
  if (w >= N) return;
  int s = __ldg(&g_rowstart[w]);
  int e = __ldg(&g_rowend[w]);
  const __half2* M = (const __half2*)g_Mh4;
  float2 a0 = make_float2(0.f, 0.f), a1 = make_float2(0.f, 0.f);
  int j = s;
  for (; j + 2 <= e; j += 2) {
    int s0 = __ldg(&g_csrsrc[j]);
    int s1 = __ldg(&g_csrsrc[j + 1]);
    float2 v0 = __half22float2(__ldg(&M[(size_t)s0 * 32 + lane]));
    float2 v1 = __half22float2(__ldg(&M[(size_t)s1 * 32 + lane]));
    a0.x += v0.x; a0.y += v0.y;
    a1.x += v1.x; a1.y += v1.y;
  }
  if (j < e) {
    int s0 = __ldg(&g_csrsrc[j]);
    float2 v0 = __half22float2(__ldg(&M[(size_t)s0 * 32 + lane]));
    a0.x += v0.x; a0.y += v0.y;
  }
  ((float2*)g_agg4)[(size_t)w * 32 + lane] =
      make_float2(a0.x + a1.x, a0.y + a1.y);
}

// ---------------------------------------------------------------------------
// msg: M = relu(h @ W1 + b1) @ W2 + b2   (fp16 HMMA, fp32 accumulate)
// 256 threads (8 warps), tile 128 rows x 64 cols. Warp grid 4x2, each warp a
// 32x32 output region (2x2 wmma 16x16 frags).
// smem: as_h[128][72] half, w1h[64][72] half, w2h[64][72] half, fs[128][72] f32
// ---------------------------------------------------------------------------
#define LDA 72
__global__ void __launch_bounds__(256) msg_kernel(
    const float* __restrict__ W1, const float* __restrict__ B1,
    const float* __restrict__ W2, const float* __restrict__ B2, int N) {
  extern __shared__ char smc[];
  __half* as_h = (__half*)smc;          // 128 x 72
  __half* w1h = as_h + 128 * LDA;       // 64 x 72
  __half* w2h = w1h + 64 * LDA;         // 64 x 72
  float* fs = (float*)(w2h + 64 * LDA); // 128 x 72

  int tid = threadIdx.x;
  int rb = blockIdx.x * NROWS;

  // weights -> half smem
  for (int i = tid; i < 4096; i += 256) {
    int k = i >> 6, c = i & 63;
    w1h[k * LDA + c] = __float2half(__ldg(W1 + i));
    w2h[k * LDA + c] = __float2half(__ldg(W2 + i));
  }
  // A (h rows) -> half smem; each thread converts half a row (32 floats)
  {
    int r = tid >> 1, hh = tid & 1;
    int grow = rb + r;
    __half* dstp = as_h + r * LDA + hh * 32;
    if (grow < N) {
      const float4* src =
          (const float4*)((const float*)g_h4 + (size_t)grow * 64) + hh * 8;
#pragma unroll
      for (int q = 0; q < 8; q++) {
        float4 v = src[q];
        dstp[q * 4 + 0] = __float2half(v.x);
        dstp[q * 4 + 1] = __float2half(v.y);
        dstp[q * 4 + 2] = __float2half(v.z);
        dstp[q * 4 + 3] = __float2half(v.w);
      }
    } else {
#pragma unroll
      for (int q = 0; q < 32; q++) dstp[q] = __float2half(0.f);
    }
  }
  __syncthreads();

  int wid = tid >> 5;
  int wr = (wid & 3) * 32, wc = (wid >> 2) * 32;

  wmma::fragment<wmma::accumulator, 16, 16, 16, float> acc[2][2];
#pragma unroll
  for (int i = 0; i < 2; i++)
#pragma unroll
    for (int j = 0; j < 2; j++) wmma::fill_fragment(acc[i][j], 0.f);

#pragma unroll
  for (int k = 0; k < 64; k += 16) {
    wmma::fragment<wmma::matrix_a, 16, 16, 16, __half, wmma::row_major> af[2];
    wmma::fragment<wmma::matrix_b, 16, 16, 16, __half, wmma::row_major> bf[2];
    wmma::load_matrix_sync(af[0], as_h + wr * LDA + k, LDA);
    wmma::load_matrix_sync(af[1], as_h + (wr + 16) * LDA + k, LDA);
    wmma::load_matrix_sync(bf[0], w1h + k * LDA + wc, LDA);
    wmma::load_matrix_sync(bf[1], w1h + k * LDA + wc + 16, LDA);
#pragma unroll
    for (int i = 0; i < 2; i++)
#pragma unroll
      for (int j = 0; j < 2; j++)
        wmma::mma_sync(acc[i][j], af[i], bf[j], acc[i][j]);
  }
#pragma unroll
  for (int i = 0; i < 2; i++)
#pragma unroll
    for (int j = 0; j < 2; j++)
      wmma::store_matrix_sync(fs + (wr + 16 * i) * LDA + wc + 16 * j,
                              acc[i][j], LDA, wmma::mem_row_major);
  __syncthreads();

  // t = relu(s1 + b1) -> overwrite as_h (half)
  {
    int r = tid >> 1, c0 = (tid & 1) * 32;
#pragma unroll
    for (int q = 0; q < 32; q++) {
      int c = c0 + q;
      as_h[r * LDA + c] =
          __float2half(fmaxf(fs[r * LDA + c] + __ldg(B1 + c), 0.f));
    }
  }
  __syncthreads();

#pragma unroll
  for (int i = 0; i < 2; i++)
#pragma unroll
    for (int j = 0; j < 2; j++) wmma::fill_fragment(acc[i][j], 0.f);
#pragma unroll
  for (int k = 0; k < 64; k += 16) {
    wmma::fragment<wmma::matrix_a, 16, 16, 16, __half, wmma::row_major> af[2];
    wmma::fragment<wmma::matrix_b, 16, 16, 16, __half, wmma::row_major> bf[2];
    wmma::load_matrix_sync(af[0], as_h + wr * LDA + k, LDA);
    wmma::load_matrix_sync(af[1], as_h + (wr + 16) * LDA + k, LDA);
    wmma::load_matrix_sync(bf[0], w2h + k * LDA + wc, LDA);
    wmma::load_matrix_sync(bf[1], w2h + k * LDA + wc + 16, LDA);
#pragma unroll
    for (int i = 0; i < 2; i++)
#pragma unroll
      for (int j = 0; j < 2; j++)
        wmma::mma_sync(acc[i][j], af[i], bf[j], acc[i][j]);
  }
  __syncthreads();  // fs reads (t pass) done everywhere before overwrite
#pragma unroll
  for (int i = 0; i < 2; i++)
#pragma unroll
    for (int j = 0; j < 2; j++)
      wmma::store_matrix_sync(fs + (wr + 16 * i) * LDA + wc + 16 * j,
                              acc[i][j], LDA, wmma::mem_row_major);
  __syncthreads();

  // M (fp16) = s2 + b2
  {
    int r = tid >> 1, c0 = (tid & 1) * 32;
    int grow = rb + r;
    if (grow < N) {
      __half2* dst = (__half2*)g_Mh4 + (size_t)grow * 32 + (c0 >> 1);
#pragma unroll
      for (int q = 0; q < 16; q++) {
        int c = c0 + q * 2;
        dst[q] = __floats2half2_rn(fs[r * LDA + c] + __ldg(B2 + c),
                                   fs[r * LDA + c + 1] + __ldg(B2 + c + 1));
      }
    }
  }
}

// ---------------------------------------------------------------------------
// upd: hn = relu([h,agg] @ W1 + b1) @ W2 + b2 ; bn ; h = relu(hn + h)
// A tile 128 x 128 half (cols 0..63 = h, 64..127 = agg; agg half later
// overwritten by t). Old h kept in cols [0,64) for the residual.
// ---------------------------------------------------------------------------
#define LDU 136
__global__ void __launch_bounds__(256) upd_kernel(
    const float* __restrict__ W1, const float* __restrict__ B1,
    const float* __restrict__ W2, const float* __restrict__ B2,
    const float* __restrict__ Gm, const float* __restrict__ Bt,
    const float* __restrict__ Mn, const float* __restrict__ Vr, int N) {
  extern __shared__ char smc[];
  __half* as_h = (__half*)smc;           // 128 x 136
  __half* w1h = as_h + 128 * LDU;        // 128 x 72
  __half* w2h = w1h + 128 * LDA;         // 64 x 72
  float* fs = (float*)(w2h + 64 * LDA);  // 128 x 72
  __shared__ float scs[64], shs[64], b2s[64];

  int tid = threadIdx.x;
  int rb = blockIdx.x * NROWS;

  for (int i = tid; i < 8192; i += 256) {
    int k = i >> 6, c = i & 63;
    w1h[k * LDA + c] = __float2half(__ldg(W1 + i));
  }
  for (int i = tid; i < 4096; i += 256) {
    int k = i >> 6, c = i & 63;
    w2h[k * LDA + c] = __float2half(__ldg(W2 + i));
  }
  if (tid < 64) {
    float s = __ldg(Gm + tid) * rsqrtf(__ldg(Vr + tid) + 1e-5f);
    scs[tid] = s;
    shs[tid] = __ldg(Bt + tid) - __ldg(Mn + tid) * s;
    b2s[tid] = __ldg(B2 + tid);
  }
  {
    int r = tid >> 1, hh = tid & 1;
    int grow = rb + r;
    __half* d1 = as_h + r * LDU + hh * 32;
    __half* d2 = as_h + r * LDU + 64 + hh * 32;
    if (grow < N) {
      const float4* s1 =
          (const float4*)((const float*)g_h4 + (size_t)grow * 64) + hh * 8;
      const float4* s2 =
          (const float4*)((const float*)g_agg4 + (size_t)grow * 64) + hh * 8;
#pragma unroll
      for (int q = 0; q < 8; q++) {
        float4 v = s1[q];
        d1[q * 4 + 0] = __float2half(v.x);
        d1[q * 4 + 1] = __float2half(v.y);
        d1[q * 4 + 2] = __float2half(v.z);
        d1[q * 4 + 3] = __float2half(v.w);
        float4 u = s2[q];
        d2[q * 4 + 0] = __float2half(u.x);
        d2[q * 4 + 1] = __float2half(u.y);
        d2[q * 4 + 2] = __float2half(u.z);
        d2[q * 4 + 3] = __float2half(u.w);
      }
    } else {
#pragma unroll
      for (int q = 0; q < 32; q++) {
        d1[q] = __float2half(0.f);
        d2[q] = __float2half(0.f);
      }
    }
  }
  __syncthreads();

  int wid = tid >> 5;
  int wr = (wid & 3) * 32, wc = (wid >> 2) * 32;

  wmma::fragment<wmma::accumulator, 16, 16, 16, float> acc[2][2];
#pragma unroll
  for (int i = 0; i < 2; i++)
#pragma unroll
    for (int j = 0; j < 2; j++) wmma::fill_fragment(acc[i][j], 0.f);

#pragma unroll
  for (int k = 0; k < 128; k += 16) {
    wmma::fragment<wmma::matrix_a, 16, 16, 16, __half, wmma::row_major> af[2];
    wmma::fragment<wmma::matrix_b, 16, 16, 16, __half, wmma::row_major> bf[2];
    wmma::load_matrix_sync(af[0], as_h + wr * LDU + k, LDU);
    wmma::load_matrix_sync(af[1], as_h + (wr + 16) * LDU + k, LDU);
    wmma::load_matrix_sync(bf[0], w1h + k * LDA + wc, LDA);
    wmma::load_matrix_sync(bf[1], w1h + k * LDA + wc + 16, LDA);
#pragma unroll
    for (int i = 0; i < 2; i++)
#pragma unroll
      for (int j = 0; j < 2; j++)
        wmma::mma_sync(acc[i][j], af[i], bf[j], acc[i][j]);
  }
#pragma unroll
  for (int i = 0; i < 2; i++)
#pragma unroll
    for (int j = 0; j < 2; j++)
      wmma::store_matrix_sync(fs + (wr + 16 * i) * LDA + wc + 16 * j,
                              acc[i][j], LDA, wmma::mem_row_major);
  __syncthreads();

  // t = relu(s1 + b1) -> as_h cols [64,128)  (agg no longer needed)
  {
    int r = tid >> 1, c0 = (tid & 1) * 32;
#pragma unroll
    for (int q = 0; q < 32; q++) {
      int c = c0 + q;
      as_h[r * LDU + 64 + c] =
          __float2half(fmaxf(fs[r * LDA + c] + __ldg(B1 + c), 0.f));
    }
  }
  __syncthreads();

#pragma unroll
  for (int i = 0; i < 2; i++)
#pragma unroll
    for (int j = 0; j < 2; j++) wmma::fill_fragment(acc[i][j], 0.f);
#pragma unroll
  for (int k = 0; k < 64; k += 16) {
    wmma::fragment<wmma::matrix_a, 16, 16, 16, __half, wmma::row_major> af[2];
    wmma::fragment<wmma::matrix_b, 16, 16, 16, __half, wmma::row_major> bf[2];
    wmma::load_matrix_sync(af[0], as_h + wr * LDU + 64 + k, LDU);
    wmma::load_matrix_sync(af[1], as_h + (wr + 16) * LDU + 64 + k, LDU);
    wmma::load_matrix_sync(bf[0], w2h + k * LDA + wc, LDA);
    wmma::load_matrix_sync(bf[1], w2h + k * LDA + wc + 16, LDA);
#pragma unroll
    for (int i = 0; i < 2; i++)
#pragma unroll
      for (int j = 0; j < 2; j++)
        wmma::mma_sync(acc[i][j], af[i], bf[j], acc[i][j]);
  }
  __syncthreads();
#pragma unroll
  for (int i = 0; i < 2; i++)
#pragma unroll
    for (int j = 0; j < 2; j++)
      wmma::store_matrix_sync(fs + (wr + 16 * i) * LDA + wc + 16 * j,
                              acc[i][j], LDA, wmma::mem_row_major);
  __syncthreads();

  // h = relu(bn(s2 + b2) + h_old)
  {
    int r = tid >> 1, c0 = (tid & 1) * 32;
    int grow = rb + r;
    if (grow < N) {
      float* dst = (float*)g_h4 + (size_t)grow * 64 + c0;
#pragma unroll
      for (int q = 0; q < 8; q++) {
        float4 o;
        float* op = (float*)&o;
#pragma unroll
        for (int u = 0; u < 4; u++) {
          int c = c0 + q * 4 + u;
          float hn = fs[r * LDA + c] + b2s[c];
          float hold = __half2float(as_h[r * LDU + c]);
          op[u] = fmaxf(fmaf(hn, scs[c], shs[c]) + hold, 0.f);
        }
        ((float4*)dst)[q] = o;
      }
    }
  }
}

// ---------------------------------------------------------------------------
// out = relu(h[:NQ] @ out_w1 + b1) @ out_w2 + b2   (64->32->1, warp per node)
// ---------------------------------------------------------------------------
__global__ void __launch_bounds__(256) out_kernel(
    const float* __restrict__ w1, const float* __restrict__ b1,
    const float* __restrict__ w2, const float* __restrict__ b2,
    float* __restrict__ out, int NQ) {
  int warp = (blockIdx.x * blockDim.x + threadIdx.x) >> 5;
  int lane = threadIdx.x & 31;
  if (warp >= NQ) return;
  const float* h = (const float*)g_h4;
  float2 hv = ((const float2*)(h + (size_t)warp * 64))[lane];
  float acc = __ldg(b1 + lane);
#pragma unroll
  for (int kk = 0; kk < 32; kk++) {
    float hx = __shfl_sync(0xffffffffu, hv.x, kk);
    float hy = __shfl_sync(0xffffffffu, hv.y, kk);
    acc = fmaf(hx, __ldg(w1 + (2 * kk) * 32 + lane), acc);
    acc = fmaf(hy, __ldg(w1 + (2 * kk + 1) * 32 + lane), acc);
  }
  float v = fmaxf(acc, 0.f) * __ldg(w2 + lane);
#pragma unroll
  for (int o = 16; o; o >>= 1) v += __shfl_down_sync(0xffffffffu, v, o);
  if (lane == 0) out[warp] = v + __ldg(b2);
}

// ---------------------------------------------------------------------------
extern "C" void kernel_launch(void* const* d_in, const int* in_sizes, int n_in,
                              void* d_out, int out_size) {
  int off = (n_in >= 21) ? 1 : 0;
  const float* x      = (const float*)d_in[0];
  const int*   ei     = (const int*)d_in[1];
  const float* w_in   = (const float*)d_in[2 + off];
  const float* b_in   = (const float*)d_in[3 + off];
  const float* msg_w1 = (const float*)d_in[4 + off];
  const float* msg_b1 = (const float*)d_in[5 + off];
  const float* msg_w2 = (const float*)d_in[6 + off];
  const float* msg_b2 = (const float*)d_in[7 + off];
  const float* upd_w1 = (const float*)d_in[8 + off];
  const float* upd_b1 = (const float*)d_in[9 + off];
  const float* upd_w2 = (const float*)d_in[10 + off];
  const float* upd_b2 = (const float*)d_in[11 + off];
  const float* bn_g   = (const float*)d_in[12 + off];
  const float* bn_b   = (const float*)d_in[13 + off];
  const float* bn_m   = (const float*)d_in[14 + off];
  const float* bn_v   = (const float*)d_in[15 + off];
  const float* out_w1 = (const float*)d_in[16 + off];
  const float* out_b1 = (const float*)d_in[17 + off];
  const float* out_w2 = (const float*)d_in[18 + off];
  const float* out_b2 = (const float*)d_in[19 + off];

  int N = in_sizes[0] / 3;
  int E = in_sizes[1] / 2;
  int L = in_sizes[4 + off] / (64 * 64);
  int NQ = out_size;

  const int MSG_SMEM = (128 * LDA + 2 * 64 * LDA) * 2 + 128 * LDA * 4;  // 72KB
  const int UPD_SMEM =
      (128 * LDU + 128 * LDA + 64 * LDA) * 2 + 128 * LDA * 4;           // 97KB
  cudaFuncSetAttribute(msg_kernel, cudaFuncAttributeMaxDynamicSharedMemorySize,
                       MSG_SMEM);
  cudaFuncSetAttribute(upd_kernel, cudaFuncAttributeMaxDynamicSharedMemorySize,
                       UPD_SMEM);

  int gb = (N + NROWS - 1) / NROWS;
  int nb_scan = (N + 1023) / 1024;

  input_kernel<<<(N * 64 + 255) / 256, 256>>>(x, w_in, b_in, N);

  zero_counts_kernel<<<(N + 255) / 256, 256>>>(N);
  hist_kernel<<<(E + 255) / 256, 256>>>(ei, E);
  scan1_kernel<<<nb_scan, 1024>>>(N);
  scan2_kernel<<<1, 32>>>(nb_scan);
  scan3_kernel<<<(N + 255) / 256, 256>>>(N);
  fill_kernel<<<(E + 255) / 256, 256>>>(ei, E);

  for (int l = 0; l < L; l++) {
    msg_kernel<<<gb, 256, MSG_SMEM>>>(msg_w1 + l * 4096, msg_b1 + l * 64,
                                      msg_w2 + l * 4096, msg_b2 + l * 64, N);
    gather_kernel<<<(N * 32 + 255) / 256, 256>>>(N);
    upd_kernel<<<gb, 256, UPD_SMEM>>>(
        upd_w1 + l * 8192, upd_b1 + l * 64, upd_w2 + l * 4096, upd_b2 + l * 64,
        bn_g + l * 64, bn_b + l * 64, bn_m + l * 64, bn_v + l * 64, N);
  }

  out_kernel<<<(NQ * 32 + 255) / 256, 256>>>(out_w1, out_b1, out_w2, out_b2,
                                             (float*)d_out, NQ);
}